// round 7
// baseline (speedup 1.0000x reference)
#include <cuda_runtime.h>

// Cubic B-spline prefilter (Unser), DCT-II mirror boundaries, as a truncated
// symmetric FIR: h[k] = sqrt(3) * p^|k|, p = sqrt(3)-2, radius 8 (17 taps).
// Pipeline chunked per (batch,channel) volume (28.3 MB) so the W+H
// intermediate stays L2-resident for the D pass. Every launch is a single
// perfectly balanced wave:
//   kWH: 576 blocks (occ 5, cap 740), 2 strips each  -> 1152 tiles
//   kD : 576 blocks (occ 4, cap 592), 192x64 tiles   -> single wave

#define NAX   192
#define KR    8
#define NT    (2*KR + 1)        // 17 taps
#define TW    32                // kWH strip output width
#define LC    (TW + 2*KR)       // 48 loaded cols (halo +-8)
#define P1    49                // kWH smem pitch (odd -> conflict-free)
#define SEGH  16                // H-phase outputs/thread
#define WLH   (SEGH + 2*KR)     // 32
#define TDW   64                // kD tile width
#define SEGD  24
#define WLD   (SEGD + 2*KR)     // 40
#define TPBF  192
#define TPBD  256
#define VOL   (NAX * NAX * NAX)

// taps T[k] = sqrt(3)*p^|k-8| as compile-time floats -> FFMA-imm in SASS (rt=1)
#define DECL_TAPS const float T[NT] = { \
     4.6023585e-05f, -1.7176230e-04f,  6.4102556e-04f, -2.3923386e-03f, \
     8.9283341e-03f, -3.3320997e-02f,  1.2435565e-01f, -4.6410161e-01f, \
     1.7320508e+00f, -4.6410161e-01f,  1.2435565e-01f, -3.3320997e-02f, \
     8.9283341e-03f, -2.3923386e-03f,  6.4102556e-04f, -1.7176230e-04f, \
     4.6023585e-05f }

__device__ __forceinline__ int mirror_idx(int i) {
    i = (i < 0) ? (-1 - i) : i;                  // half-sample left reflect
    return (i >= NAX) ? (2 * NAX - 1 - i) : i;   // half-sample right reflect
}

// ---------------------------------------------------------------------------
// Fused W+H pass: block = slice*3 + c, processes strips {2c, 2c+1}.
// Per strip: load 192x48 -> in-place W filter (register delay line) ->
// H filter with direct coalesced STG. One 192x49 smem buffer.
// ---------------------------------------------------------------------------
__global__ __launch_bounds__(TPBF, 5) void kWH(const float* __restrict__ in,
                                               float* __restrict__ out) {
    extern __shared__ float s[];   // [192][P1]

    const int tid   = threadIdx.x;              // 0..191
    const int c     = blockIdx.x % 3;
    const int slice = blockIdx.x / 3;
    const int base  = slice * (NAX * NAX);

    DECL_TAPS;

#pragma unroll 1
    for (int it = 0; it < 2; ++it) {
        const int wbase = (2 * c + it) * TW;
        if (it) __syncthreads();                // strip0 smem reads done before reload

        // ---- load 192 x 48 (coalesced LDG, high MLP)
#pragma unroll
        for (int k = 0; k < (NAX * LC) / TPBF; ++k) {   // 48 iterations
            int i   = tid + TPBF * k;
            int row = i / LC;
            int cc  = i - row * LC;
            s[row * P1 + cc] = in[base + row * NAX + mirror_idx(wbase - KR + cc)];
        }
        __syncthreads();

        // ---- W filter in place: thread owns row `tid` (17-deep delay line)
        {
            float* rp = &s[tid * P1];           // stride-49 -> conflict-free
            float win[NT];
#pragma unroll
            for (int m = 0; m < NT - 1; ++m) win[m] = rp[m];
#pragma unroll
            for (int j = 0; j < TW; ++j) {
                win[NT - 1] = rp[j + 2 * KR];
                float acc = 0.0f;
#pragma unroll
                for (int k = 0; k < NT; ++k) acc = fmaf(T[k], win[k], acc);
                rp[j + KR] = acc;
#pragma unroll
                for (int m = 0; m < NT - 1; ++m) win[m] = win[m + 1];
            }
        }
        __syncthreads();

        // ---- H filter: 384 tasks = (w 0..31) x (hseg 0..11 of 16 outputs)
#pragma unroll
        for (int r = 0; r < 2; ++r) {
            const int t    = tid + TPBF * r;
            const int w    = t & (TW - 1);
            const int hseg = t >> 5;             // 0..11
            const int h0   = hseg * SEGH;

            float win[WLH];
#pragma unroll
            for (int m = 0; m < WLH; ++m)
                win[m] = s[mirror_idx(h0 - KR + m) * P1 + KR + w];

            float* o = out + base + wbase + w;
#pragma unroll
            for (int j = 0; j < SEGH; ++j) {
                float acc = 0.0f;
#pragma unroll
                for (int k = 0; k < NT; ++k) acc = fmaf(T[k], win[j + k], acc);
                o[(h0 + j) * NAX] = acc;         // 128B coalesced per j
            }
        }
    }
}

// ---------------------------------------------------------------------------
// D pass, in place, ONE volume per launch. Tile: 192(d) x 64(w).
// Grid: blockIdx = hh*3 + c  (576 blocks = one wave at occ 4).
// Reads hit L2 (chunk just written by kWH); stores overwrite dirty lines.
// ---------------------------------------------------------------------------
__global__ __launch_bounds__(TPBD, 4) void kD(float* buf) {
    __shared__ float s[NAX][TDW];
    const int tid = threadIdx.x;
    const int c   = blockIdx.x % 3;
    const int hh  = blockIdx.x / 3;
    const int base = hh * NAX + c * TDW;

    // ---- load 192 x 64: warp = 128B contiguous half-row; high MLP
    const int w0 = tid & (TDW - 1);
    const int r0 = tid >> 6;                    // 0..3
#pragma unroll
    for (int k = 0; k < NAX / 4; ++k)           // 48 iterations
        s[r0 + 4 * k][w0] = buf[base + (r0 + 4 * k) * (NAX * NAX) + w0];
    __syncthreads();

    DECL_TAPS;

    // ---- filter: 512 tasks = (w 0..63) x (dseg 0..7 of 24 outputs)
#pragma unroll
    for (int r = 0; r < 2; ++r) {
        const int t   = tid + TPBD * r;
        const int w   = t & (TDW - 1);
        const int seg = t >> 6;                  // 0..7
        const int a0  = seg * SEGD;

        float win[WLD];
#pragma unroll
        for (int m = 0; m < WLD; ++m)
            win[m] = s[mirror_idx(a0 - KR + m)][w];

#pragma unroll
        for (int j = 0; j < SEGD; ++j) {
            float acc = 0.0f;
#pragma unroll
            for (int k = 0; k < NT; ++k) acc = fmaf(T[k], win[j + k], acc);
            buf[base + (a0 + j) * (NAX * NAX) + w] = acc;   // coalesced per j
        }
    }
}

extern "C" void kernel_launch(void* const* d_in, const int* in_sizes, int n_in,
                              void* d_out, int out_size) {
    const float* x = (const float*)d_in[0];
    float* y = (float*)d_out;

    const int B = 8;   // 4 batch * 2 channel
    const int smemWH = NAX * P1 * (int)sizeof(float);   // 37632 B

    static int attr_set = 0;
    if (!attr_set) {
        cudaFuncSetAttribute(kWH, cudaFuncAttributeMaxDynamicSharedMemorySize, smemWH);
        attr_set = 1;
    }

    const int gridWH = NAX * 3;   // 576 blocks, 2 strips each
    const int gridD  = NAX * 3;   // 576 blocks, 192x64 tiles

    for (int b = 0; b < B; ++b) {
        const float* xb = x + (size_t)b * VOL;
        float*       yb = y + (size_t)b * VOL;
        kWH<<<gridWH, TPBF, smemWH>>>(xb, yb);  // W+H fused: chunk stays in L2
        kD<<<gridD, TPBD>>>(yb);                // D axis: L2 reads, in place
    }
}

// round 8
// speedup vs baseline: 1.3500x; 1.3500x over previous
#include <cuda_runtime.h>

// Cubic B-spline prefilter (Unser), DCT-II mirror boundaries, as a truncated
// symmetric FIR: h[k] = sqrt(3) * p^|k|, p = sqrt(3)-2, radius 8 (17 taps).
//
// Pipeline chunked per (batch,channel) volume (28.3 MB) so the W+H
// intermediate stays L2-resident for the D pass (DRAM traffic ~halves),
// AND pipelined across two streams so kD(b) overlaps kWH(b+1):
//   capture stream: kWH(0) kWH(1) ... kWH(7)        (critical path)
//   stream2:        kD(0)->after kWH(0), kD(1)->after kWH(1), ...
// Fork/join via events is graph-capturable and becomes graph edges.

#define NAX   192
#define KR    8
#define NT    (2*KR + 1)        // 17 taps
#define TW    32                // strip output width
#define LC    (TW + 2*KR)       // 48 loaded cols (halo +-8)
#define P1    49                // smem pitch (odd -> conflict-free both ways)
#define SEGH  16                // H-phase outputs/thread
#define WLH   (SEGH + 2*KR)     // 32
#define SEGD  24
#define WLD   (SEGD + 2*KR)     // 40
#define TPBF  192
#define TPBD  256
#define VOL   (NAX * NAX * NAX)
#define NCH   8                 // 4 batch * 2 channel

// taps T[k] = sqrt(3)*p^|k-8| as compile-time floats -> FFMA-imm in SASS (rt=1)
#define DECL_TAPS const float T[NT] = { \
     4.6023585e-05f, -1.7176230e-04f,  6.4102556e-04f, -2.3923386e-03f, \
     8.9283341e-03f, -3.3320997e-02f,  1.2435565e-01f, -4.6410161e-01f, \
     1.7320508e+00f, -4.6410161e-01f,  1.2435565e-01f, -3.3320997e-02f, \
     8.9283341e-03f, -2.3923386e-03f,  6.4102556e-04f, -1.7176230e-04f, \
     4.6023585e-05f }

__device__ __forceinline__ int mirror_idx(int i) {
    i = (i < 0) ? (-1 - i) : i;                  // half-sample left reflect
    return (i >= NAX) ? (2 * NAX - 1 - i) : i;   // half-sample right reflect
}

// ---------------------------------------------------------------------------
// Fused W+H pass, one 192 x 32 strip per block, one 192x49 smem buffer.
// Grid covers ONE volume (1152 blocks; staggered arrival smooths phases).
// ---------------------------------------------------------------------------
__global__ __launch_bounds__(TPBF, 5) void kWH(const float* __restrict__ in,
                                               float* __restrict__ out) {
    extern __shared__ float s[];   // [192][P1]

    const int tid   = threadIdx.x;              // 0..191
    const int strip = blockIdx.x % (NAX / TW);  // 6 strips; adjacent -> L2 halo reuse
    const int slice = blockIdx.x / (NAX / TW);
    const int base  = slice * (NAX * NAX);
    const int wbase = strip * TW;

    // ---- load 192 x 48 (coalesced LDG, independent -> high MLP)
#pragma unroll
    for (int k = 0; k < (NAX * LC) / TPBF; ++k) {   // 48 iterations
        int i   = tid + TPBF * k;
        int row = i / LC;
        int c   = i - row * LC;
        s[row * P1 + c] = in[base + row * NAX + mirror_idx(wbase - KR + c)];
    }
    __syncthreads();

    DECL_TAPS;

    // ---- W filter in place: thread owns row `tid` (17-deep register delay line)
    {
        float* rp = &s[tid * P1];   // lanes: stride-49 -> conflict-free
        float win[NT];
#pragma unroll
        for (int m = 0; m < NT - 1; ++m) win[m] = rp[m];   // preload cols 0..15
#pragma unroll
        for (int j = 0; j < TW; ++j) {
            win[NT - 1] = rp[j + 2 * KR];                  // read col j+16
            float acc = 0.0f;
#pragma unroll
            for (int k = 0; k < NT; ++k) acc = fmaf(T[k], win[k], acc);
            rp[j + KR] = acc;                              // write col j+8
#pragma unroll
            for (int m = 0; m < NT - 1; ++m) win[m] = win[m + 1];  // reg rotate
        }
    }
    __syncthreads();

    // ---- H filter: 384 tasks = (w 0..31) x (hseg 0..11 of 16 outputs)
#pragma unroll
    for (int r = 0; r < 2; ++r) {
        const int t    = tid + TPBF * r;
        const int w    = t & (TW - 1);
        const int hseg = t >> 5;                 // 0..11
        const int h0   = hseg * SEGH;

        float win[WLH];
#pragma unroll
        for (int m = 0; m < WLH; ++m)
            win[m] = s[mirror_idx(h0 - KR + m) * P1 + KR + w];  // lane = w -> conflict-free

        float* o = out + base + wbase + w;
#pragma unroll
        for (int j = 0; j < SEGH; ++j) {
            float acc = 0.0f;
#pragma unroll
            for (int k = 0; k < NT; ++k) acc = fmaf(T[k], win[j + k], acc);
            o[(h0 + j) * NAX] = acc;             // 128B coalesced per j
        }
    }
}

// ---------------------------------------------------------------------------
// D pass (stride 192*192), in place, ONE volume per launch.
// Tile 192(d) x 32(w), 1152 blocks. Reads hit L2 (chunk just written).
// ---------------------------------------------------------------------------
__global__ __launch_bounds__(TPBD, 5) void kD(float* buf) {
    __shared__ float s[NAX][32];
    const int tid = threadIdx.x;
    const int c   = blockIdx.x % (NAX / 32);
    const int hh  = blockIdx.x / (NAX / 32);
    const int base = hh * NAX + c * 32;

    const int w  = tid & 31;
    const int a4 = tid >> 5;
#pragma unroll
    for (int k = 0; k < NAX / 8; ++k)   // 24 outstanding LDG/thread
        s[a4 + 8 * k][w] = buf[base + (a4 + 8 * k) * (NAX * NAX) + w];
    __syncthreads();

    DECL_TAPS;
    const int a0 = (tid >> 5) * SEGD;
    float win[WLD];
#pragma unroll
    for (int m = 0; m < WLD; ++m)
        win[m] = s[mirror_idx(a0 - KR + m)][w];

#pragma unroll
    for (int j = 0; j < SEGD; ++j) {
        float acc = 0.0f;
#pragma unroll
        for (int k = 0; k < NT; ++k) acc = fmaf(T[k], win[j + k], acc);
        buf[base + (a0 + j) * (NAX * NAX) + w] = acc;     // 128B coalesced per j
    }
}

extern "C" void kernel_launch(void* const* d_in, const int* in_sizes, int n_in,
                              void* d_out, int out_size) {
    const float* x = (const float*)d_in[0];
    float* y = (float*)d_out;

    const int smemWH = NAX * P1 * (int)sizeof(float);   // 37632 B

    static int init_done = 0;
    static cudaStream_t s2;
    static cudaEvent_t evF[NCH];    // kWH(b) done -> gate kD(b)
    static cudaEvent_t evJoin;      // last kD done -> join capture stream
    if (!init_done) {
        cudaFuncSetAttribute(kWH, cudaFuncAttributeMaxDynamicSharedMemorySize, smemWH);
        cudaStreamCreateWithFlags(&s2, cudaStreamNonBlocking);
        for (int b = 0; b < NCH; ++b)
            cudaEventCreateWithFlags(&evF[b], cudaEventDisableTiming);
        cudaEventCreateWithFlags(&evJoin, cudaEventDisableTiming);
        init_done = 1;
    }

    const int gridWH = NAX * (NAX / TW);   // 1152 blocks per volume
    const int gridD  = NAX * (NAX / 32);   // 1152 blocks per volume

    for (int b = 0; b < NCH; ++b) {
        const float* xb = x + (size_t)b * VOL;
        float*       yb = y + (size_t)b * VOL;
        kWH<<<gridWH, TPBF, smemWH>>>(xb, yb);   // capture stream (critical path)
        cudaEventRecord(evF[b], 0);
        cudaStreamWaitEvent(s2, evF[b], 0);
        kD<<<gridD, TPBD, 0, s2>>>(yb);          // overlaps kWH(b+1)
    }
    cudaEventRecord(evJoin, s2);                 // join: capture stream waits
    cudaStreamWaitEvent(0, evJoin, 0);           // for the last kD
}